// round 7
// baseline (speedup 1.0000x reference)
#include <cuda_runtime.h>

#define HIDDEN  20
#define NPAIR   (HIDDEN / 2)    // 10 packed k-pairs
#define N_MID   8

#define CB     0.5f
#define CC     0.5f
#define CSIGMA 1.0f
#define CBF    0.5f
#define CCF    0.9f

typedef unsigned long long ull;

// ---------------- packed f32x2 helpers ----------------
__device__ __forceinline__ ull pack2(float lo, float hi) {
    ull r;
    asm("mov.b64 %0, {%1, %2};" : "=l"(r) : "f"(lo), "f"(hi));
    return r;
}
__device__ __forceinline__ void unpack2(ull p, float& lo, float& hi) {
    asm("mov.b64 {%0, %1}, %2;" : "=f"(lo), "=f"(hi) : "l"(p));
}
__device__ __forceinline__ ull fma2(ull a, ull b, ull c) {
    ull r;
    asm("fma.rn.f32x2 %0, %1, %2, %3;" : "=l"(r) : "l"(a), "l"(b), "l"(c));
    return r;
}
__device__ __forceinline__ ull add2(ull a, ull b) {
    ull r;
    asm("add.rn.f32x2 %0, %1, %2;" : "=l"(r) : "l"(a), "l"(b));
    return r;
}
__device__ __forceinline__ float hsum2(ull p) {
    float lo, hi;
    unpack2(p, lo, hi);
    return lo + hi;
}

// tanh via EX2 + approx reciprocal (rel err ~2^-22; slack vs 1e-3 is huge).
__device__ __forceinline__ float tanh_acc(float z) {
    float az = fabsf(z);
    float e  = __expf(-2.0f * az);
    float r  = __fdividef(1.0f - e, 1.0f + e);
    return copysignf(r, z);
}

// One mid layer for a lane-pair-split thread.
// curA/curB: this thread's two streams as k-pairs (even lane: h,u; odd: v,w).
// Produces newA/newB. s0 = (lane is even).
__device__ __forceinline__ void mid_layer(const float* __restrict__ Wl,   // [20][20] natural
                                          const float* __restrict__ bl,   // [20]
                                          const ull curA[NPAIR],
                                          const ull curB[NPAIR],
                                          ull newA[NPAIR],
                                          ull newB[NPAIR],
                                          bool s0)
{
    float tmpA = 0.0f, tmpB = 0.0f;       // j-even staging for pair packing
    #pragma unroll
    for (int j = 0; j < HIDDEN; j++) {
        // packed dot products along K: 5x LDS.128 -> 10 weight pairs
        ull a0 = 0ull, a1 = 0ull, b0 = 0ull, b1 = 0ull;
        const float4* __restrict__ Wrow =
            reinterpret_cast<const float4*>(&Wl[j * HIDDEN]);
        #pragma unroll
        for (int q4 = 0; q4 < 5; q4++) {
            const float4 wq = Wrow[q4];            // 4 weights (16B aligned: 80*j+16*q4)
            const ull wp0 = pack2(wq.x, wq.y);
            const ull wp1 = pack2(wq.z, wq.w);
            const int q = 2 * q4;
            a0 = fma2(wp0, curA[q],     a0);
            b0 = fma2(wp0, curB[q],     b0);
            a1 = fma2(wp1, curA[q + 1], a1);
            b1 = fma2(wp1, curB[q + 1], b1);
        }
        float zA = hsum2(add2(a0, a1));            // even: z      | odd: zv
        const float zB = hsum2(add2(b0, b1));      // even: zu     | odd: zw
        if (s0) zA += bl[j];

        // even lane computes tanh; odd receives 'a' via shfl
        float a = tanh_acc(zA);                    // odd computes garbage-ish; overwritten
        const float ax = __shfl_xor_sync(0xFFFFFFFFu, a, 1);
        if (!s0) a = ax;
        const float d = fmaf(-a, a, 1.0f);

        float nA, nB;
        if (s0) { nA = a;       nB = d * zB; }                 // nh, nu
        else    { nA = d * zA;  nB = fmaf(d, zB, -2.0f * a * nA * zA); }  // nv, nw

        if ((j & 1) == 0) { tmpA = nA; tmpB = nB; }
        else {
            newA[j >> 1] = pack2(tmpA, nA);
            newB[j >> 1] = pack2(tmpB, nB);
        }
    }
}

__global__ __launch_bounds__(128, 4)   // ~128-reg cap -> 4 CTAs/SM = 16 warps
void pde_mlp_kernel(const float* __restrict__ x,
                    const float* __restrict__ W_in,
                    const float* __restrict__ b_in,
                    const float* __restrict__ W_mid,
                    const float* __restrict__ b_mid,
                    const float* __restrict__ W_out,
                    const float* __restrict__ b_out,
                    float* __restrict__ out,
                    int n)
{
    __shared__ __align__(16) float sW[N_MID * HIDDEN * HIDDEN];   // natural fp32, 12.8 KB
    __shared__ float sB[N_MID * HIDDEN];
    __shared__ __align__(8) float sWout[HIDDEN];
    __shared__ float sWin[HIDDEN * 2];
    __shared__ float sbin[HIDDEN];
    __shared__ float sbout;

    const int tid = threadIdx.x;
    for (int i = tid; i < N_MID * HIDDEN * HIDDEN; i += blockDim.x) sW[i] = W_mid[i];
    for (int i = tid; i < N_MID * HIDDEN; i += blockDim.x)          sB[i] = b_mid[i];
    for (int i = tid; i < HIDDEN; i += blockDim.x) { sWout[i] = W_out[i]; sbin[i] = b_in[i]; }
    for (int i = tid; i < HIDDEN * 2; i += blockDim.x)              sWin[i] = W_in[i];
    if (tid == 0) sbout = b_out[0];
    __syncthreads();

    const int gid = blockIdx.x * blockDim.x + tid;     // 2 threads per point
    const int p   = gid >> 1;
    if (p >= n) return;
    const bool s0 = ((tid & 1) == 0);                  // even lane: (h,u); odd: (v,w)

    const float2 xi = reinterpret_cast<const float2*>(x)[p];
    const float t = xi.x, xs = xi.y;

    // Per-thread state: two streams as k-pairs; ping-pong A/B.
    ull curA[NPAIR], curB[NPAIR], nxtA[NPAIR], nxtB[NPAIR];

    // ---- input layer (both lanes compute z fully; keep own streams) ----
    {
        float tmpA = 0.0f, tmpB = 0.0f;
        #pragma unroll
        for (int j = 0; j < HIDDEN; j++) {
            const float w0 = sWin[2 * j], w1 = sWin[2 * j + 1];
            const float z = fmaf(w0, t, fmaf(w1, xs, sbin[j]));
            const float a = tanh_acc(z);
            const float d = fmaf(-a, a, 1.0f);
            float nA, nB;
            if (s0) { nA = a;       nB = d * w0; }                       // h, u
            else    { nA = d * w1;  nB = -2.0f * a * nA * w1; }          // v, w
            if ((j & 1) == 0) { tmpA = nA; tmpB = nB; }
            else {
                curA[j >> 1] = pack2(tmpA, nA);
                curB[j >> 1] = pack2(tmpB, nB);
            }
        }
    }

    // ---- mid layers, ping-pong ----
    #pragma unroll 1
    for (int lp = 0; lp < N_MID; lp += 2) {
        mid_layer(&sW[(lp    ) * HIDDEN * HIDDEN], &sB[(lp    ) * HIDDEN],
                  curA, curB, nxtA, nxtB, s0);
        mid_layer(&sW[(lp + 1) * HIDDEN * HIDDEN], &sB[(lp + 1) * HIDDEN],
                  nxtA, nxtB, curA, curB, s0);
    }

    // ---- output layer: packed dots with Wout ----
    ull fA0 = 0ull, fA1 = 0ull, fB0 = 0ull, fB1 = 0ull;
    #pragma unroll
    for (int q4 = 0; q4 < 5; q4++) {
        const float4 wq = reinterpret_cast<const float4*>(sWout)[q4];
        const ull wp0 = pack2(wq.x, wq.y);
        const ull wp1 = pack2(wq.z, wq.w);
        const int q = 2 * q4;
        fA0 = fma2(wp0, curA[q],     fA0);
        fB0 = fma2(wp0, curB[q],     fB0);
        fA1 = fma2(wp1, curA[q + 1], fA1);
        fB1 = fma2(wp1, curB[q + 1], fB1);
    }
    float rA = hsum2(add2(fA0, fA1));   // even: f (pre-bias) | odd: fv
    float rB = hsum2(add2(fB0, fB1));   // even: fu           | odd: fw
    if (s0) rA += sbout;

    // exchange: even receives (fv, fw) from odd
    const float gA = __shfl_xor_sync(0xFFFFFFFFu, rA, 1);
    const float gB = __shfl_xor_sync(0xFFFFFFFFu, rB, 1);

    if (s0) {
        const float f = rA, fu = rB, fv = gA, fw = gB;
        const float pde = CBF * xs * xs
                        + fu
                        + 0.5f * CSIGMA * CSIGMA * fw
                        + CB * xs * fv
                        - (CC * CC / (4.0f * CCF)) * fv * fv;
        out[p]     = f;
        out[n + p] = pde;
    }
}

extern "C" void kernel_launch(void* const* d_in, const int* in_sizes, int n_in,
                              void* d_out, int out_size)
{
    const float* x     = (const float*)d_in[0];
    const float* W_in  = (const float*)d_in[1];
    const float* b_in  = (const float*)d_in[2];
    const float* W_mid = (const float*)d_in[3];
    const float* b_mid = (const float*)d_in[4];
    const float* W_out = (const float*)d_in[5];
    const float* b_out = (const float*)d_in[6];
    float* out = (float*)d_out;

    const int n = in_sizes[0] / 2;     // x is (N, 2)
    const int threads = 128;
    const int total   = 2 * n;         // 2 threads per point
    const int blocks  = (total + threads - 1) / threads;
    pde_mlp_kernel<<<blocks, threads>>>(x, W_in, b_in, W_mid, b_mid,
                                        W_out, b_out, out, n);
}